// round 1
// baseline (speedup 1.0000x reference)
#include <cuda_runtime.h>
#include <stdint.h>

#define QIN   90
#define QOUT  60
#define OPAD  64
#define KMAX  16
#define CINV  32
#define COUTV 32
#define H1V   32
#define H2V   64
#define DMAXV 1.0f
#define MAXB  4

// Per-(b,o) compacted tables produced by prep_kernel.
__device__ float         g_Mw[MAXB * OPAD * KMAX * CINV];   // [b][o][k][c], masked weights
__device__ unsigned char g_sel[MAXB * OPAD * KMAX];         // [b][o][k], gathered input index

// ---------------------------------------------------------------------------
// Kernel 1: distances + top-K selection + WeightNet MLP -> compact tables
// grid = B*OPAD blocks, 128 threads
// ---------------------------------------------------------------------------
__global__ void prep_kernel(const float* __restrict__ ang_in, const float* __restrict__ ang_out,
                            const float* __restrict__ W1, const float* __restrict__ b1,
                            const float* __restrict__ W2, const float* __restrict__ b2,
                            const float* __restrict__ W3, const float* __restrict__ b3,
                            int B)
{
    int bo = blockIdx.x;
    int b = bo / OPAD, o = bo % OPAD;
    int tid = threadIdx.x;

    if (o >= QOUT) {  // padded o slots: zero weights so main kernel adds nothing
        for (int i = tid; i < KMAX * CINV; i += blockDim.x)
            g_Mw[(b * OPAD + o) * KMAX * CINV + i] = 0.f;
        if (tid < KMAX) g_sel[(b * OPAD + o) * KMAX + tid] = 0;
        return;
    }

    __shared__ float sd[QIN], sbd[QIN];
    __shared__ int   ssel[KMAX];
    __shared__ float smask[KMAX], skd[KMAX], skbd[KMAX];
    __shared__ float sW2[H1V * H2V], sW3[H2V * CINV];
    __shared__ float sW1a[H1V], sW1b[H1V], sb1[H1V], sb2[H2V], sb3[CINV];
    __shared__ float sh1[KMAX][H1V], sh2[KMAX][H2V];

    for (int i = tid; i < H1V * H2V; i += 128) sW2[i] = W2[i];
    for (int i = tid; i < H2V * CINV; i += 128) sW3[i] = W3[i];
    if (tid < H2V) sb2[tid] = b2[tid];
    if (tid < CINV) sb3[tid] = b3[tid];
    if (tid < H1V) { sW1a[tid] = W1[3 * H1V + tid]; sW1b[tid] = W1[4 * H1V + tid]; sb1[tid] = b1[tid]; }

    float aox = ang_out[(b * QOUT + o) * 3 + 0];
    float aoy = ang_out[(b * QOUT + o) * 3 + 1];
    float aoz = ang_out[(b * QOUT + o) * 3 + 2];
    float nout = sqrtf(aox * aox + aoy * aoy + aoz * aoz);
    float ivo = (nout > 0.f) ? 1.f / nout : 0.f;
    float uox = aox * ivo, uoy = aoy * ivo, uoz = aoz * ivo;

    if (tid < QIN) {
        float x = ang_in[(b * QIN + tid) * 3 + 0];
        float y = ang_in[(b * QIN + tid) * 3 + 1];
        float z = ang_in[(b * QIN + tid) * 3 + 2];
        float nin = sqrtf(x * x + y * y + z * z);
        float ivi = (nin > 0.f) ? 1.f / nin : 0.f;
        float dot = (x * ivi) * uox + (y * ivi) * uoy + (z * ivi) * uoz;
        // min(arccos(clip(dot)), arccos(clip(-dot))) == arccos(min(|dot|, 1-EPS))
        float d = acosf(fminf(fabsf(dot), 1.0f - 1e-7f));
        sd[tid] = d;
        sbd[tid] = nout - nin;
    }
    __syncthreads();

    // Stable rank (matches argsort(argsort) tie semantics), scatter top-16
    if (tid < QIN) {
        float dt = sd[tid];
        int r = 0;
        for (int j = 0; j < QIN; j++) {
            float dj = sd[j];
            r += (dj < dt || (dj == dt && j < tid)) ? 1 : 0;
        }
        if (r < KMAX) {
            ssel[r] = tid;
            smask[r] = (dt <= DMAXV) ? 1.f : 0.f;
            skd[r] = dt;
            skbd[r] = sbd[tid];
        }
    }
    __syncthreads();

    // MLP: 128 threads = 16 k-slots x 8 lanes
    int k = tid >> 3, ln = tid & 7;
    {
        float d = skd[k], bd = skbd[k];
        #pragma unroll
        for (int jj = 0; jj < 4; jj++) {
            int j = ln * 4 + jj;
            float h = fmaf(d, sW1a[j], fmaf(bd, sW1b[j], sb1[j]));
            sh1[k][j] = fmaxf(h, 0.f);
        }
    }
    __syncthreads();
    #pragma unroll
    for (int ll = 0; ll < 8; ll++) {
        int l = ln * 8 + ll;
        float acc = sb2[l];
        #pragma unroll 8
        for (int j = 0; j < H1V; j++) acc = fmaf(sh1[k][j], sW2[j * H2V + l], acc);
        sh2[k][l] = fmaxf(acc, 0.f);
    }
    __syncthreads();
    float m = smask[k];
    #pragma unroll
    for (int cc = 0; cc < 4; cc++) {
        int c = ln * 4 + cc;
        float acc = sb3[c];
        #pragma unroll 8
        for (int l = 0; l < H2V; l++) acc = fmaf(sh2[k][l], sW3[l * CINV + c], acc);
        g_Mw[((b * OPAD + o) * KMAX + k) * CINV + c] = m * acc;
    }
    if (ln == 0) g_sel[(b * OPAD + o) * KMAX + k] = (unsigned char)ssel[k];
}

// ---------------------------------------------------------------------------
// Kernel 2: persistent gather-conv + Wf epilogue
// ---------------------------------------------------------------------------
__device__ __forceinline__ void async_row(float* dst, const float* __restrict__ src, int tid)
{
    uint32_t s = (uint32_t)__cvta_generic_to_shared(dst);
    #pragma unroll
    for (int i = 0; i < 3; i++) {
        int idx = tid + i * 256;
        if (idx < (QIN * CINV) / 4)
            asm volatile("cp.async.cg.shared.global [%0], [%1], 16;\n"
                         :: "r"(s + idx * 16), "l"(src + idx * 4) : "memory");
    }
    asm volatile("cp.async.commit_group;\n" ::: "memory");
}

__global__ void __launch_bounds__(256, 1)
conv_kernel(const float* __restrict__ f_in, const float* __restrict__ Wf,
            const float* __restrict__ bias_out, float* __restrict__ out,
            int B, int N)
{
    __shared__ float fbuf[2][QIN * CINV];   // double-buffered f row (2 x 11.25 KB)
    __shared__ float aggs[OPAD][CINV];      // agg transpose staging (8 KB)

    const int tid  = threadIdx.x;
    const int lane = tid & 31;              // channel c
    const int warp = tid >> 5;
    const int wo   = warp * 8;              // this warp's o block

    float Wfr[CINV];
    #pragma unroll
    for (int c = 0; c < CINV; c++) Wfr[c] = Wf[c * COUTV + lane];
    const float biasr = bias_out[lane];

    long long R = (long long)B * N;
    long long chunk = (R + gridDim.x - 1) / gridDim.x;
    long long r0 = (long long)blockIdx.x * chunk;
    long long r1 = r0 + chunk; if (r1 > R) r1 = R;
    if (r0 >= r1) return;

    float    M[8][16];
    uint32_t ip[8][4];

    long long g = r0;
    while (g < r1) {
        int b = (int)(g / N);
        long long gend = (long long)(b + 1) * N; if (gend > r1) gend = r1;

        // Load this batch's weight/index tables into registers (amortized over ~216 rows)
        #pragma unroll
        for (int oo = 0; oo < 8; oo++) {
            const float* mp = &g_Mw[((b * OPAD + wo + oo) * KMAX) * CINV + lane];
            #pragma unroll
            for (int kk = 0; kk < 16; kk++) M[oo][kk] = mp[kk * CINV];
            const uint32_t* q = (const uint32_t*)&g_sel[(b * OPAD + wo + oo) * KMAX];
            #pragma unroll
            for (int qq = 0; qq < 4; qq++) ip[oo][qq] = q[qq];
        }

        async_row(fbuf[0], f_in + g * (QIN * CINV), tid);

        for (long long t = g; t < gend; t++) {
            int cur = (int)((t - g) & 1);
            if (t + 1 < gend) {
                async_row(fbuf[cur ^ 1], f_in + (t + 1) * (QIN * CINV), tid);
                asm volatile("cp.async.wait_group 1;\n" ::: "memory");
            } else {
                asm volatile("cp.async.wait_group 0;\n" ::: "memory");
            }
            __syncthreads();   // buffer ready; prev phase2 done -> aggs reusable

            // Phase 1: sparse gather-reduce, M in regs, f from smem (conflict-free)
            const float* fb = fbuf[cur];
            float agg[8];
            #pragma unroll
            for (int oo = 0; oo < 8; oo++) {
                float a = 0.f;
                #pragma unroll
                for (int kk = 0; kk < 16; kk++) {
                    int i = (int)((ip[oo][kk >> 2] >> ((kk & 3) * 8)) & 0xFFu);
                    a = fmaf(M[oo][kk], fb[i * CINV + lane], a);
                }
                agg[oo] = a;
            }
            #pragma unroll
            for (int oo = 0; oo < 8; oo++) aggs[wo + oo][lane] = agg[oo];
            __syncthreads();

            // Phase 2: out[o, lane] = sum_c aggs[o][c] * Wf[c][lane] + bias
            float* orow = out + (long long)t * QOUT * COUTV;
            #pragma unroll
            for (int oo = 0; oo < 8; oo++) {
                int o = wo + oo;
                if (o < QOUT) {
                    const float4* av = (const float4*)aggs[o];
                    float acc = biasr;
                    #pragma unroll
                    for (int s4 = 0; s4 < 8; s4++) {
                        float4 v = av[s4];   // LDS.128 broadcast
                        acc = fmaf(v.x, Wfr[s4 * 4 + 0], acc);
                        acc = fmaf(v.y, Wfr[s4 * 4 + 1], acc);
                        acc = fmaf(v.z, Wfr[s4 * 4 + 2], acc);
                        acc = fmaf(v.w, Wfr[s4 * 4 + 3], acc);
                    }
                    orow[o * COUTV + lane] = acc;
                }
            }
        }
        g = gend;
    }
}

// ---------------------------------------------------------------------------
extern "C" void kernel_launch(void* const* d_in, const int* in_sizes, int n_in,
                              void* d_out, int out_size)
{
    const float* ang_in   = (const float*)d_in[0];
    const float* ang_out  = (const float*)d_in[1];
    const float* f_in     = (const float*)d_in[2];
    const float* W1       = (const float*)d_in[3];
    const float* b1       = (const float*)d_in[4];
    const float* W2       = (const float*)d_in[5];
    const float* b2       = (const float*)d_in[6];
    const float* W3       = (const float*)d_in[7];
    const float* b3       = (const float*)d_in[8];
    const float* Wf       = (const float*)d_in[9];
    const float* bias_out = (const float*)d_in[10];
    float* out = (float*)d_out;

    int B = in_sizes[0] / (QIN * 3);
    int N = in_sizes[2] / (B * QIN * CINV);

    prep_kernel<<<B * OPAD, 128>>>(ang_in, ang_out, W1, b1, W2, b2, W3, b3, B);

    int nsm = 148;
    cudaDeviceGetAttribute(&nsm, cudaDevAttrMultiProcessorCount, 0);
    conv_kernel<<<nsm, 256>>>(f_in, Wf, bias_out, out, B, N);
}

// round 2
// speedup vs baseline: 1.4278x; 1.4278x over previous
#include <cuda_runtime.h>
#include <stdint.h>

#define QIN   90
#define QOUT  60
#define OPAD  64
#define KMAX  16
#define CINV  32
#define COUTV 32
#define H1V   32
#define H2V   64
#define DMAXV 1.0f
#define MAXB  4
#define ROWF  (QIN * CINV)   // 2880 floats per (b,n) row

// Per-(b,o) compacted tables produced by prep_kernel.
__device__ float         g_Mw[MAXB * OPAD * KMAX * CINV];   // [b][o][k][c], masked weights
__device__ unsigned char g_sel[MAXB * OPAD * KMAX];         // [b][o][k], gathered input index

// ---------------------------------------------------------------------------
// Kernel 1: distances + top-K selection + WeightNet MLP -> compact tables
// grid = B*OPAD blocks, 128 threads
// ---------------------------------------------------------------------------
__global__ void prep_kernel(const float* __restrict__ ang_in, const float* __restrict__ ang_out,
                            const float* __restrict__ W1, const float* __restrict__ b1,
                            const float* __restrict__ W2, const float* __restrict__ b2,
                            const float* __restrict__ W3, const float* __restrict__ b3,
                            int B)
{
    int bo = blockIdx.x;
    int b = bo / OPAD, o = bo % OPAD;
    int tid = threadIdx.x;

    if (o >= QOUT) {  // padded o slots: zero weights so main kernel adds nothing
        for (int i = tid; i < KMAX * CINV; i += blockDim.x)
            g_Mw[(b * OPAD + o) * KMAX * CINV + i] = 0.f;
        if (tid < KMAX) g_sel[(b * OPAD + o) * KMAX + tid] = 0;
        return;
    }

    __shared__ float sd[QIN], sbd[QIN];
    __shared__ int   ssel[KMAX];
    __shared__ float smask[KMAX], skd[KMAX], skbd[KMAX];
    __shared__ float sW2[H1V * H2V], sW3[H2V * CINV];
    __shared__ float sW1a[H1V], sW1b[H1V], sb1[H1V], sb2[H2V], sb3[CINV];
    __shared__ float sh1[KMAX][H1V], sh2[KMAX][H2V];

    for (int i = tid; i < H1V * H2V; i += 128) sW2[i] = W2[i];
    for (int i = tid; i < H2V * CINV; i += 128) sW3[i] = W3[i];
    if (tid < H2V) sb2[tid] = b2[tid];
    if (tid < CINV) sb3[tid] = b3[tid];
    if (tid < H1V) { sW1a[tid] = W1[3 * H1V + tid]; sW1b[tid] = W1[4 * H1V + tid]; sb1[tid] = b1[tid]; }

    float aox = ang_out[(b * QOUT + o) * 3 + 0];
    float aoy = ang_out[(b * QOUT + o) * 3 + 1];
    float aoz = ang_out[(b * QOUT + o) * 3 + 2];
    float nout = sqrtf(aox * aox + aoy * aoy + aoz * aoz);
    float ivo = (nout > 0.f) ? 1.f / nout : 0.f;
    float uox = aox * ivo, uoy = aoy * ivo, uoz = aoz * ivo;

    if (tid < QIN) {
        float x = ang_in[(b * QIN + tid) * 3 + 0];
        float y = ang_in[(b * QIN + tid) * 3 + 1];
        float z = ang_in[(b * QIN + tid) * 3 + 2];
        float nin = sqrtf(x * x + y * y + z * z);
        float ivi = (nin > 0.f) ? 1.f / nin : 0.f;
        float dot = (x * ivi) * uox + (y * ivi) * uoy + (z * ivi) * uoz;
        // min(arccos(clip(dot)), arccos(clip(-dot))) == arccos(min(|dot|, 1-EPS))
        float d = acosf(fminf(fabsf(dot), 1.0f - 1e-7f));
        sd[tid] = d;
        sbd[tid] = nout - nin;
    }
    __syncthreads();

    // Stable rank (matches argsort(argsort) tie semantics), scatter top-16
    if (tid < QIN) {
        float dt = sd[tid];
        int r = 0;
        for (int j = 0; j < QIN; j++) {
            float dj = sd[j];
            r += (dj < dt || (dj == dt && j < tid)) ? 1 : 0;
        }
        if (r < KMAX) {
            ssel[r] = tid;
            smask[r] = (dt <= DMAXV) ? 1.f : 0.f;
            skd[r] = dt;
            skbd[r] = sbd[tid];
        }
    }
    __syncthreads();

    // MLP: 128 threads = 16 k-slots x 8 lanes
    int k = tid >> 3, ln = tid & 7;
    {
        float d = skd[k], bd = skbd[k];
        #pragma unroll
        for (int jj = 0; jj < 4; jj++) {
            int j = ln * 4 + jj;
            float h = fmaf(d, sW1a[j], fmaf(bd, sW1b[j], sb1[j]));
            sh1[k][j] = fmaxf(h, 0.f);
        }
    }
    __syncthreads();
    #pragma unroll
    for (int ll = 0; ll < 8; ll++) {
        int l = ln * 8 + ll;
        float acc = sb2[l];
        #pragma unroll 8
        for (int j = 0; j < H1V; j++) acc = fmaf(sh1[k][j], sW2[j * H2V + l], acc);
        sh2[k][l] = fmaxf(acc, 0.f);
    }
    __syncthreads();
    float m = smask[k];
    #pragma unroll
    for (int cc = 0; cc < 4; cc++) {
        int c = ln * 4 + cc;
        float acc = sb3[c];
        #pragma unroll 8
        for (int l = 0; l < H2V; l++) acc = fmaf(sh2[k][l], sW3[l * CINV + c], acc);
        g_Mw[((b * OPAD + o) * KMAX + k) * CINV + c] = m * acc;
    }
    if (ln == 0) g_sel[(b * OPAD + o) * KMAX + k] = (unsigned char)ssel[k];
}

// ---------------------------------------------------------------------------
// Kernel 2: persistent gather-conv + Wf epilogue
//   gridDim.y = 2 o-halves (each block covers 32 output dirs, warp owns 4)
//   2 rows per iteration, double-buffered pairs via cp.async
// ---------------------------------------------------------------------------
__device__ __forceinline__ void async_rows(float* dst, const float* __restrict__ src,
                                           int nr, int tid)
{
    uint32_t s = (uint32_t)__cvta_generic_to_shared(dst);
    int total = nr * (ROWF / 4);   // float4 count: 720 or 1440
    #pragma unroll
    for (int i = 0; i < 6; i++) {
        int idx = tid + i * 256;
        if (idx < total)
            asm volatile("cp.async.cg.shared.global [%0], [%1], 16;\n"
                         :: "r"(s + idx * 16), "l"(src + idx * 4) : "memory");
    }
    asm volatile("cp.async.commit_group;\n" ::: "memory");
}

__global__ void __launch_bounds__(256, 2)
conv_kernel(const float* __restrict__ f_in, const float* __restrict__ Wf,
            const float* __restrict__ bias_out, float* __restrict__ out,
            int B, int N)
{
    __shared__ float fbuf[2][2 * ROWF];      // double-buffered row PAIRS (2 x 22.5 KB)
    __shared__ float aggs[2][32][CINV];      // per-row agg staging (8 KB)

    const int tid   = threadIdx.x;
    const int lane  = tid & 31;              // channel c
    const int warp  = tid >> 5;
    const int obase = blockIdx.y * 32;       // this block's o-half
    const int wo    = warp * 4;              // local o block within half

    float Wfr[CINV];
    #pragma unroll
    for (int c = 0; c < CINV; c++) Wfr[c] = Wf[c * COUTV + lane];
    const float biasr = bias_out[lane];

    long long R = (long long)B * N;
    long long chunk = (R + gridDim.x - 1) / gridDim.x;
    long long r0 = (long long)blockIdx.x * chunk;
    long long r1 = r0 + chunk; if (r1 > R) r1 = R;
    if (r0 >= r1) return;

    float    M[4][16];
    uint32_t ip[4][4];

    long long g = r0;
    while (g < r1) {
        int b = (int)(g / N);
        long long gend = (long long)(b + 1) * N; if (gend > r1) gend = r1;

        // Load this batch's weight/index tables (amortized over ~200 rows)
        #pragma unroll
        for (int oo = 0; oo < 4; oo++) {
            int og = obase + wo + oo;
            const float* mp = &g_Mw[((b * OPAD + og) * KMAX) * CINV + lane];
            #pragma unroll
            for (int kk = 0; kk < 16; kk++) M[oo][kk] = mp[kk * CINV];
            const uint32_t* q = (const uint32_t*)&g_sel[(b * OPAD + og) * KMAX];
            #pragma unroll
            for (int qq = 0; qq < 4; qq++) ip[oo][qq] = q[qq];
        }

        {
            int nfirst = (int)((gend - g) < 2 ? (gend - g) : 2);
            async_rows(fbuf[0], f_in + g * ROWF, nfirst, tid);
        }

        int pb = 0;
        for (long long t = g; t < gend; t += 2, pb ^= 1) {
            long long tn = t + 2;
            if (tn < gend) {
                int nr = (int)((gend - tn) < 2 ? (gend - tn) : 2);
                async_rows(fbuf[pb ^ 1], f_in + tn * ROWF, nr, tid);
                asm volatile("cp.async.wait_group 1;\n" ::: "memory");
            } else {
                asm volatile("cp.async.wait_group 0;\n" ::: "memory");
            }
            __syncthreads();   // pair ready; also fences previous iter's buffer reads

            const int nrows = (int)((gend - t) < 2 ? (gend - t) : 2);

            // Phase 1: sparse gather-reduce (M in regs, f from smem, conflict-free)
            for (int r = 0; r < nrows; r++) {
                const float* fr = fbuf[pb] + r * ROWF;
                float a[4];
                #pragma unroll
                for (int oo = 0; oo < 4; oo++) {
                    float acc = 0.f;
                    #pragma unroll
                    for (int kk = 0; kk < 16; kk++) {
                        int i = (int)((ip[oo][kk >> 2] >> ((kk & 3) * 8)) & 0xFFu);
                        acc = fmaf(M[oo][kk], fr[i * CINV + lane], acc);
                    }
                    a[oo] = acc;
                }
                #pragma unroll
                for (int oo = 0; oo < 4; oo++) aggs[r][wo + oo][lane] = a[oo];
            }
            __syncthreads();

            // Phase 2: out[o, lane] = sum_c aggs[r][o][c] * Wf[c][lane] + bias
            for (int r = 0; r < nrows; r++) {
                float* orow = out + (t + r) * (QOUT * COUTV);
                #pragma unroll
                for (int oo = 0; oo < 4; oo++) {
                    int og = obase + wo + oo;
                    if (og < QOUT) {
                        const float4* av = (const float4*)aggs[r][wo + oo];
                        float acc = biasr;
                        #pragma unroll
                        for (int s4 = 0; s4 < 8; s4++) {
                            float4 v = av[s4];   // LDS.128 broadcast
                            acc = fmaf(v.x, Wfr[s4 * 4 + 0], acc);
                            acc = fmaf(v.y, Wfr[s4 * 4 + 1], acc);
                            acc = fmaf(v.z, Wfr[s4 * 4 + 2], acc);
                            acc = fmaf(v.w, Wfr[s4 * 4 + 3], acc);
                        }
                        orow[og * COUTV + lane] = acc;
                    }
                }
            }
        }
        g = gend;
    }
}

// ---------------------------------------------------------------------------
extern "C" void kernel_launch(void* const* d_in, const int* in_sizes, int n_in,
                              void* d_out, int out_size)
{
    const float* ang_in   = (const float*)d_in[0];
    const float* ang_out  = (const float*)d_in[1];
    const float* f_in     = (const float*)d_in[2];
    const float* W1       = (const float*)d_in[3];
    const float* b1       = (const float*)d_in[4];
    const float* W2       = (const float*)d_in[5];
    const float* b2       = (const float*)d_in[6];
    const float* W3       = (const float*)d_in[7];
    const float* b3       = (const float*)d_in[8];
    const float* Wf       = (const float*)d_in[9];
    const float* bias_out = (const float*)d_in[10];
    float* out = (float*)d_out;

    int B = in_sizes[0] / (QIN * 3);
    int N = in_sizes[2] / (B * QIN * CINV);

    prep_kernel<<<B * OPAD, 128>>>(ang_in, ang_out, W1, b1, W2, b2, W3, b3, B);

    int nsm = 148;
    cudaDeviceGetAttribute(&nsm, cudaDevAttrMultiProcessorCount, 0);
    dim3 grid(nsm, 2);
    conv_kernel<<<grid, 256>>>(f_in, Wf, bias_out, out, B, N);
}

// round 3
// speedup vs baseline: 1.5859x; 1.1108x over previous
#include <cuda_runtime.h>
#include <stdint.h>

#define QIN   90
#define QOUT  60
#define OPAD  64
#define KMAX  16
#define CINV  32
#define COUTV 32
#define H1V   32
#define H2V   64
#define DMAXV 1.0f
#define MAXB  4
#define ROWF  (QIN * CINV)   // 2880 floats per (b,n) row
#define NRB   4              // rows per iteration
#define FB_FLOATS (2 * NRB * ROWF)
#define AG_FLOATS (NRB * 32 * CINV)
#define SMEM_BYTES ((FB_FLOATS + AG_FLOATS) * 4)

// Per-(b,o) compacted tables produced by prep_kernel.
__device__ float         g_Mw[MAXB * OPAD * KMAX * CINV];   // [b][o][k][c], masked weights
__device__ unsigned char g_sel[MAXB * OPAD * KMAX];         // [b][o][k], gathered input index

// ---------------------------------------------------------------------------
// Kernel 1: distances + top-K selection + WeightNet MLP -> compact tables
// ---------------------------------------------------------------------------
__global__ void prep_kernel(const float* __restrict__ ang_in, const float* __restrict__ ang_out,
                            const float* __restrict__ W1, const float* __restrict__ b1,
                            const float* __restrict__ W2, const float* __restrict__ b2,
                            const float* __restrict__ W3, const float* __restrict__ b3,
                            int B)
{
    int bo = blockIdx.x;
    int b = bo / OPAD, o = bo % OPAD;
    int tid = threadIdx.x;

    if (o >= QOUT) {  // padded o slots: zero weights so main kernel adds nothing
        for (int i = tid; i < KMAX * CINV; i += blockDim.x)
            g_Mw[(b * OPAD + o) * KMAX * CINV + i] = 0.f;
        if (tid < KMAX) g_sel[(b * OPAD + o) * KMAX + tid] = 0;
        return;
    }

    __shared__ float sd[QIN], sbd[QIN];
    __shared__ int   ssel[KMAX];
    __shared__ float smask[KMAX], skd[KMAX], skbd[KMAX];
    __shared__ float sW2[H1V * H2V], sW3[H2V * CINV];
    __shared__ float sW1a[H1V], sW1b[H1V], sb1[H1V], sb2[H2V], sb3[CINV];
    __shared__ float sh1[KMAX][H1V], sh2[KMAX][H2V];

    for (int i = tid; i < H1V * H2V; i += 128) sW2[i] = W2[i];
    for (int i = tid; i < H2V * CINV; i += 128) sW3[i] = W3[i];
    if (tid < H2V) sb2[tid] = b2[tid];
    if (tid < CINV) sb3[tid] = b3[tid];
    if (tid < H1V) { sW1a[tid] = W1[3 * H1V + tid]; sW1b[tid] = W1[4 * H1V + tid]; sb1[tid] = b1[tid]; }

    float aox = ang_out[(b * QOUT + o) * 3 + 0];
    float aoy = ang_out[(b * QOUT + o) * 3 + 1];
    float aoz = ang_out[(b * QOUT + o) * 3 + 2];
    float nout = sqrtf(aox * aox + aoy * aoy + aoz * aoz);
    float ivo = (nout > 0.f) ? 1.f / nout : 0.f;
    float uox = aox * ivo, uoy = aoy * ivo, uoz = aoz * ivo;

    if (tid < QIN) {
        float x = ang_in[(b * QIN + tid) * 3 + 0];
        float y = ang_in[(b * QIN + tid) * 3 + 1];
        float z = ang_in[(b * QIN + tid) * 3 + 2];
        float nin = sqrtf(x * x + y * y + z * z);
        float ivi = (nin > 0.f) ? 1.f / nin : 0.f;
        float dot = (x * ivi) * uox + (y * ivi) * uoy + (z * ivi) * uoz;
        float d = acosf(fminf(fabsf(dot), 1.0f - 1e-7f));
        sd[tid] = d;
        sbd[tid] = nout - nin;
    }
    __syncthreads();

    if (tid < QIN) {
        float dt = sd[tid];
        int r = 0;
        for (int j = 0; j < QIN; j++) {
            float dj = sd[j];
            r += (dj < dt || (dj == dt && j < tid)) ? 1 : 0;
        }
        if (r < KMAX) {
            ssel[r] = tid;
            smask[r] = (dt <= DMAXV) ? 1.f : 0.f;
            skd[r] = dt;
            skbd[r] = sbd[tid];
        }
    }
    __syncthreads();

    int k = tid >> 3, ln = tid & 7;
    {
        float d = skd[k], bd = skbd[k];
        #pragma unroll
        for (int jj = 0; jj < 4; jj++) {
            int j = ln * 4 + jj;
            float h = fmaf(d, sW1a[j], fmaf(bd, sW1b[j], sb1[j]));
            sh1[k][j] = fmaxf(h, 0.f);
        }
    }
    __syncthreads();
    #pragma unroll
    for (int ll = 0; ll < 8; ll++) {
        int l = ln * 8 + ll;
        float acc = sb2[l];
        #pragma unroll 8
        for (int j = 0; j < H1V; j++) acc = fmaf(sh1[k][j], sW2[j * H2V + l], acc);
        sh2[k][l] = fmaxf(acc, 0.f);
    }
    __syncthreads();
    float m = smask[k];
    #pragma unroll
    for (int cc = 0; cc < 4; cc++) {
        int c = ln * 4 + cc;
        float acc = sb3[c];
        #pragma unroll 8
        for (int l = 0; l < H2V; l++) acc = fmaf(sh2[k][l], sW3[l * CINV + c], acc);
        g_Mw[((b * OPAD + o) * KMAX + k) * CINV + c] = m * acc;
    }
    if (ln == 0) g_sel[(b * OPAD + o) * KMAX + k] = (unsigned char)ssel[k];
}

// ---------------------------------------------------------------------------
// Kernel 2: persistent gather-conv + Wf epilogue
//   gridDim.y = 2 o-halves, warp owns 4 o's, 4 rows per iteration
// ---------------------------------------------------------------------------
__device__ __forceinline__ void async_rows(float* dst, const float* __restrict__ src,
                                           int nr, int tid)
{
    uint32_t s = (uint32_t)__cvta_generic_to_shared(dst);
    int total = nr * (ROWF / 4);   // float4 count, up to 2880
    #pragma unroll
    for (int i = 0; i < 12; i++) {
        int idx = tid + i * 256;
        if (idx < total)
            asm volatile("cp.async.cg.shared.global [%0], [%1], 16;\n"
                         :: "r"(s + idx * 16), "l"(src + idx * 4) : "memory");
    }
    asm volatile("cp.async.commit_group;\n" ::: "memory");
}

// Phase 1 for NR rows, fully unrolled when NR is a compile-time constant.
template<int NR>
__device__ __forceinline__ void phase1(const float* __restrict__ fb, float* __restrict__ aggs,
                                       const float (&M)[4][16], const uint32_t (&ip)[4][4],
                                       int wo, int lane)
{
    float acc[NR][4];
    #pragma unroll
    for (int r = 0; r < NR; r++)
        #pragma unroll
        for (int oo = 0; oo < 4; oo++) acc[r][oo] = 0.f;

    #pragma unroll
    for (int oo = 0; oo < 4; oo++) {
        #pragma unroll
        for (int kk = 0; kk < 16; kk++) {
            int i = (int)((ip[oo][kk >> 2] >> ((kk & 3) * 8)) & 0xFFu);
            float m = M[oo][kk];
            #pragma unroll
            for (int r = 0; r < NR; r++)
                acc[r][oo] = fmaf(m, fb[r * ROWF + i * CINV + lane], acc[r][oo]);
        }
    }
    #pragma unroll
    for (int r = 0; r < NR; r++)
        #pragma unroll
        for (int oo = 0; oo < 4; oo++)
            aggs[(r * 32 + wo + oo) * CINV + lane] = acc[r][oo];
}

__global__ void __launch_bounds__(256, 2)
conv_kernel(const float* __restrict__ f_in, const float* __restrict__ Wf,
            const float* __restrict__ bias_out, float* __restrict__ out,
            int B, int N)
{
    extern __shared__ float smem[];
    float* fbuf = smem;                 // [2][NRB * ROWF]
    float* aggs = smem + FB_FLOATS;     // [NRB][32][CINV]

    const int tid   = threadIdx.x;
    const int lane  = tid & 31;         // channel c
    const int warp  = tid >> 5;
    const int obase = blockIdx.y * 32;  // this block's o-half
    const int wo    = warp * 4;         // local o block within half

    float Wfr[CINV];
    #pragma unroll
    for (int c = 0; c < CINV; c++) Wfr[c] = Wf[c * COUTV + lane];
    const float biasr = bias_out[lane];

    long long R = (long long)B * N;
    long long chunk = (R + gridDim.x - 1) / gridDim.x;
    long long r0 = (long long)blockIdx.x * chunk;
    long long r1 = r0 + chunk; if (r1 > R) r1 = R;
    if (r0 >= r1) return;

    float    M[4][16];
    uint32_t ip[4][4];

    long long g = r0;
    while (g < r1) {
        int b = (int)(g / N);
        long long gend = (long long)(b + 1) * N; if (gend > r1) gend = r1;

        #pragma unroll
        for (int oo = 0; oo < 4; oo++) {
            int og = obase + wo + oo;
            const float* mp = &g_Mw[((b * OPAD + og) * KMAX) * CINV + lane];
            #pragma unroll
            for (int kk = 0; kk < 16; kk++) M[oo][kk] = mp[kk * CINV];
            const uint32_t* q = (const uint32_t*)&g_sel[(b * OPAD + og) * KMAX];
            #pragma unroll
            for (int qq = 0; qq < 4; qq++) ip[oo][qq] = q[qq];
        }

        {
            int nfirst = (int)((gend - g) < NRB ? (gend - g) : NRB);
            async_rows(fbuf, f_in + g * ROWF, nfirst, tid);
        }

        int pb = 0;
        for (long long t = g; t < gend; t += NRB, pb ^= 1) {
            long long tn = t + NRB;
            if (tn < gend) {
                int nr = (int)((gend - tn) < NRB ? (gend - tn) : NRB);
                async_rows(fbuf + (pb ^ 1) * (NRB * ROWF), f_in + tn * ROWF, nr, tid);
                asm volatile("cp.async.wait_group 1;\n" ::: "memory");
            } else {
                asm volatile("cp.async.wait_group 0;\n" ::: "memory");
            }
            __syncthreads();   // batch ready; fences previous iter's buffer/agg reads

            const int nrows = (int)((gend - t) < NRB ? (gend - t) : NRB);
            const float* fb = fbuf + pb * (NRB * ROWF);

            if (nrows == NRB) {
                phase1<NRB>(fb, aggs, M, ip, wo, lane);
            } else {
                for (int r = 0; r < nrows; r++) phase1<1>(fb + r * ROWF, aggs + r * 32 * CINV, M, ip, wo, lane);
            }
            __syncthreads();

            // Phase 2: out[o, lane] = sum_c aggs[r][o][c] * Wf[c][lane] + bias
            for (int r = 0; r < nrows; r++) {
                float* orow = out + (t + r) * (QOUT * COUTV);
                #pragma unroll
                for (int oo = 0; oo < 4; oo++) {
                    int og = obase + wo + oo;
                    if (og < QOUT) {
                        const float4* av = (const float4*)(aggs + (r * 32 + wo + oo) * CINV);
                        float acc = biasr;
                        #pragma unroll
                        for (int s4 = 0; s4 < 8; s4++) {
                            float4 v = av[s4];   // LDS.128 broadcast
                            acc = fmaf(v.x, Wfr[s4 * 4 + 0], acc);
                            acc = fmaf(v.y, Wfr[s4 * 4 + 1], acc);
                            acc = fmaf(v.z, Wfr[s4 * 4 + 2], acc);
                            acc = fmaf(v.w, Wfr[s4 * 4 + 3], acc);
                        }
                        orow[og * COUTV + lane] = acc;
                    }
                }
            }
        }
        g = gend;
    }
}

// ---------------------------------------------------------------------------
extern "C" void kernel_launch(void* const* d_in, const int* in_sizes, int n_in,
                              void* d_out, int out_size)
{
    const float* ang_in   = (const float*)d_in[0];
    const float* ang_out  = (const float*)d_in[1];
    const float* f_in     = (const float*)d_in[2];
    const float* W1       = (const float*)d_in[3];
    const float* b1       = (const float*)d_in[4];
    const float* W2       = (const float*)d_in[5];
    const float* b2       = (const float*)d_in[6];
    const float* W3       = (const float*)d_in[7];
    const float* b3       = (const float*)d_in[8];
    const float* Wf       = (const float*)d_in[9];
    const float* bias_out = (const float*)d_in[10];
    float* out = (float*)d_out;

    int B = in_sizes[0] / (QIN * 3);
    int N = in_sizes[2] / (B * QIN * CINV);

    cudaFuncSetAttribute(conv_kernel, cudaFuncAttributeMaxDynamicSharedMemorySize, SMEM_BYTES);

    prep_kernel<<<B * OPAD, 128>>>(ang_in, ang_out, W1, b1, W2, b2, W3, b3, B);

    int nsm = 148;
    cudaDeviceGetAttribute(&nsm, cudaDevAttrMultiProcessorCount, 0);
    dim3 grid(nsm, 2);
    conv_kernel<<<grid, 256, SMEM_BYTES>>>(f_in, Wf, bias_out, out, B, N);
}

// round 5
// speedup vs baseline: 2.1947x; 1.3838x over previous
#include <cuda_runtime.h>
#include <stdint.h>

#define QIN   90
#define QOUT  60
#define OPAD  64
#define KMAX  16
#define CINV  32
#define COUTV 32
#define H1V   32
#define H2V   64
#define DMAXV 1.0f
#define MAXB  4
#define ROWF  (QIN * CINV)   // 2880 floats per (b,n) row
#define NRB   8              // rows per iteration
#define NTH   512
#define FB_FLOATS (2 * NRB * ROWF)
#define AG_FLOATS (NRB * 32 * CINV)
#define WF_FLOATS (CINV * COUTV)
#define SMEM_BYTES ((FB_FLOATS + AG_FLOATS + WF_FLOATS) * 4)

// Per-(b,o) compacted tables produced by prep_kernel.
__device__ float         g_Mw[MAXB * OPAD * KMAX * CINV];   // [b][o][k][c], masked weights
__device__ unsigned char g_sel[MAXB * OPAD * KMAX];         // [b][o][k], gathered input index

// ---------------------------------------------------------------------------
// Kernel 1: distances + top-K selection + WeightNet MLP -> compact tables
// ---------------------------------------------------------------------------
__global__ void prep_kernel(const float* __restrict__ ang_in, const float* __restrict__ ang_out,
                            const float* __restrict__ W1, const float* __restrict__ b1,
                            const float* __restrict__ W2, const float* __restrict__ b2,
                            const float* __restrict__ W3, const float* __restrict__ b3,
                            int B)
{
    int bo = blockIdx.x;
    int b = bo / OPAD, o = bo % OPAD;
    int tid = threadIdx.x;

    if (o >= QOUT) {  // padded o slots: zero weights so main kernel adds nothing
        for (int i = tid; i < KMAX * CINV; i += blockDim.x)
            g_Mw[(b * OPAD + o) * KMAX * CINV + i] = 0.f;
        if (tid < KMAX) g_sel[(b * OPAD + o) * KMAX + tid] = 0;
        return;
    }

    __shared__ float sd[QIN], sbd[QIN];
    __shared__ int   ssel[KMAX];
    __shared__ float smask[KMAX], skd[KMAX], skbd[KMAX];
    __shared__ float sW2[H1V * H2V], sW3[H2V * CINV];
    __shared__ float sW1a[H1V], sW1b[H1V], sb1[H1V], sb2[H2V], sb3[CINV];
    __shared__ float sh1[KMAX][H1V], sh2[KMAX][H2V];

    for (int i = tid; i < H1V * H2V; i += 128) sW2[i] = W2[i];
    for (int i = tid; i < H2V * CINV; i += 128) sW3[i] = W3[i];
    if (tid < H2V) sb2[tid] = b2[tid];
    if (tid < CINV) sb3[tid] = b3[tid];
    if (tid < H1V) { sW1a[tid] = W1[3 * H1V + tid]; sW1b[tid] = W1[4 * H1V + tid]; sb1[tid] = b1[tid]; }

    float aox = ang_out[(b * QOUT + o) * 3 + 0];
    float aoy = ang_out[(b * QOUT + o) * 3 + 1];
    float aoz = ang_out[(b * QOUT + o) * 3 + 2];
    float nout = sqrtf(aox * aox + aoy * aoy + aoz * aoz);
    float ivo = (nout > 0.f) ? 1.f / nout : 0.f;
    float uox = aox * ivo, uoy = aoy * ivo, uoz = aoz * ivo;

    if (tid < QIN) {
        float x = ang_in[(b * QIN + tid) * 3 + 0];
        float y = ang_in[(b * QIN + tid) * 3 + 1];
        float z = ang_in[(b * QIN + tid) * 3 + 2];
        float nin = sqrtf(x * x + y * y + z * z);
        float ivi = (nin > 0.f) ? 1.f / nin : 0.f;
        float dot = (x * ivi) * uox + (y * ivi) * uoy + (z * ivi) * uoz;
        float d = acosf(fminf(fabsf(dot), 1.0f - 1e-7f));
        sd[tid] = d;
        sbd[tid] = nout - nin;
    }
    __syncthreads();

    if (tid < QIN) {
        float dt = sd[tid];
        int r = 0;
        for (int j = 0; j < QIN; j++) {
            float dj = sd[j];
            r += (dj < dt || (dj == dt && j < tid)) ? 1 : 0;
        }
        if (r < KMAX) {
            ssel[r] = tid;
            smask[r] = (dt <= DMAXV) ? 1.f : 0.f;
            skd[r] = dt;
            skbd[r] = sbd[tid];
        }
    }
    __syncthreads();

    int k = tid >> 3, ln = tid & 7;
    {
        float d = skd[k], bd = skbd[k];
        #pragma unroll
        for (int jj = 0; jj < 4; jj++) {
            int j = ln * 4 + jj;
            float h = fmaf(d, sW1a[j], fmaf(bd, sW1b[j], sb1[j]));
            sh1[k][j] = fmaxf(h, 0.f);
        }
    }
    __syncthreads();
    #pragma unroll
    for (int ll = 0; ll < 8; ll++) {
        int l = ln * 8 + ll;
        float acc = sb2[l];
        #pragma unroll 8
        for (int j = 0; j < H1V; j++) acc = fmaf(sh1[k][j], sW2[j * H2V + l], acc);
        sh2[k][l] = fmaxf(acc, 0.f);
    }
    __syncthreads();
    float m = smask[k];
    #pragma unroll
    for (int cc = 0; cc < 4; cc++) {
        int c = ln * 4 + cc;
        float acc = sb3[c];
        #pragma unroll 8
        for (int l = 0; l < H2V; l++) acc = fmaf(sh2[k][l], sW3[l * CINV + c], acc);
        g_Mw[((b * OPAD + o) * KMAX + k) * CINV + c] = m * acc;
    }
    if (ln == 0) g_sel[(b * OPAD + o) * KMAX + k] = (unsigned char)ssel[k];
}

// ---------------------------------------------------------------------------
// Kernel 2: persistent gather-conv + Wf epilogue
//   1 CTA/SM (512 thr, 16 warps), gridDim.y = 2 o-halves, warp owns 2 o's,
//   8 rows per iteration, M in regs (32/warp), Wf staged through smem.
// ---------------------------------------------------------------------------
__device__ __forceinline__ void async_rows(float* dst, const float* __restrict__ src,
                                           int nr, int tid)
{
    uint32_t s = (uint32_t)__cvta_generic_to_shared(dst);
    int total = nr * (ROWF / 4);   // float4 count, up to 5760
    #pragma unroll
    for (int i = 0; i < 12; i++) {
        int idx = tid + i * NTH;
        if (idx < total)
            asm volatile("cp.async.cg.shared.global [%0], [%1], 16;\n"
                         :: "r"(s + idx * 16), "l"(src + idx * 4) : "memory");
    }
    asm volatile("cp.async.commit_group;\n" ::: "memory");
}

// Phase 1 for NR rows: 2 o's per warp, 16 k, NR rows of independent chains.
template<int NR>
__device__ __forceinline__ void phase1(const float* __restrict__ fb, float* __restrict__ aggs,
                                       const float (&M)[2][16], const uint32_t (&ip)[2][4],
                                       int wo, int lane)
{
    float acc[NR][2];
    #pragma unroll
    for (int r = 0; r < NR; r++)
        #pragma unroll
        for (int oo = 0; oo < 2; oo++) acc[r][oo] = 0.f;

    #pragma unroll
    for (int oo = 0; oo < 2; oo++) {
        #pragma unroll
        for (int kk = 0; kk < 16; kk++) {
            int i = (int)((ip[oo][kk >> 2] >> ((kk & 3) * 8)) & 0xFFu);
            float m = M[oo][kk];
            const float* p = fb + i * CINV + lane;
            #pragma unroll
            for (int r = 0; r < NR; r++)
                acc[r][oo] = fmaf(m, p[r * ROWF], acc[r][oo]);
        }
    }
    #pragma unroll
    for (int r = 0; r < NR; r++)
        #pragma unroll
        for (int oo = 0; oo < 2; oo++)
            aggs[(r * 32 + wo + oo) * CINV + lane] = acc[r][oo];
}

__global__ void __launch_bounds__(NTH, 1)
conv_kernel(const float* __restrict__ f_in, const float* __restrict__ Wf,
            const float* __restrict__ bias_out, float* __restrict__ out,
            int B, int N)
{
    extern __shared__ float smem[];
    float* fbuf = smem;                             // [2][NRB * ROWF]
    float* aggs = smem + FB_FLOATS;                 // [NRB][32][CINV]
    float* sWf  = smem + FB_FLOATS + AG_FLOATS;     // [CINV][COUTV]

    const int tid   = threadIdx.x;
    const int lane  = tid & 31;         // channel c
    const int warp  = tid >> 5;         // 0..15
    const int obase = blockIdx.y * 32;  // this block's o-half
    const int wo    = warp * 2;         // local o pair within half

    for (int i = tid; i < WF_FLOATS; i += NTH) sWf[i] = Wf[i];
    const float biasr = bias_out[lane];

    long long R = (long long)B * N;
    long long chunk = (R + gridDim.x - 1) / gridDim.x;
    long long r0 = (long long)blockIdx.x * chunk;
    long long r1 = r0 + chunk; if (r1 > R) r1 = R;
    if (r0 >= r1) return;

    float    M[2][16];
    uint32_t ip[2][4];

    long long g = r0;
    while (g < r1) {
        int b = (int)(g / N);
        long long gend = (long long)(b + 1) * N; if (gend > r1) gend = r1;

        // Load this batch's weight/index tables (amortized over ~420 rows)
        #pragma unroll
        for (int oo = 0; oo < 2; oo++) {
            int og = obase + wo + oo;
            const float* mp = &g_Mw[((b * OPAD + og) * KMAX) * CINV + lane];
            #pragma unroll
            for (int kk = 0; kk < 16; kk++) M[oo][kk] = mp[kk * CINV];
            const uint32_t* q = (const uint32_t*)&g_sel[(b * OPAD + og) * KMAX];
            #pragma unroll
            for (int qq = 0; qq < 4; qq++) ip[oo][qq] = q[qq];
        }

        {
            int nfirst = (int)((gend - g) < NRB ? (gend - g) : NRB);
            async_rows(fbuf, f_in + g * ROWF, nfirst, tid);
        }

        int pb = 0;
        for (long long t = g; t < gend; t += NRB, pb ^= 1) {
            long long tn = t + NRB;
            if (tn < gend) {
                int nr = (int)((gend - tn) < NRB ? (gend - tn) : NRB);
                async_rows(fbuf + (pb ^ 1) * (NRB * ROWF), f_in + tn * ROWF, nr, tid);
                asm volatile("cp.async.wait_group 1;\n" ::: "memory");
            } else {
                asm volatile("cp.async.wait_group 0;\n" ::: "memory");
            }
            __syncthreads();   // batch ready; fences previous iter's buffer reads

            const int nrows = (int)((gend - t) < NRB ? (gend - t) : NRB);
            const float* fb = fbuf + pb * (NRB * ROWF);

            if (nrows == NRB) {
                phase1<NRB>(fb, aggs, M, ip, wo, lane);
            } else {
                for (int r = 0; r < nrows; r++)
                    phase1<1>(fb + r * ROWF, aggs + r * 32 * CINV, M, ip, wo, lane);
            }
            // REQUIRED block barrier: all warps must finish reading fbuf[pb]
            // before any warp loops around and prefetches into it.
            __syncthreads();

            // Phase 2: out[o, lane] = sum_c aggs[r][o][c] * Wf[c][lane] + bias
            // Wf pulled from smem here, so its 32 regs are NOT live in phase 1.
            float wfr[CINV];
            #pragma unroll
            for (int c = 0; c < CINV; c++) wfr[c] = sWf[c * COUTV + lane];

            for (int r = 0; r < nrows; r++) {
                float* orow = out + (t + r) * (QOUT * COUTV);
                #pragma unroll
                for (int oo = 0; oo < 2; oo++) {
                    int og = obase + wo + oo;
                    if (og < QOUT) {
                        const float4* av = (const float4*)(aggs + (r * 32 + wo + oo) * CINV);
                        float acc = biasr;
                        #pragma unroll
                        for (int s4 = 0; s4 < 8; s4++) {
                            float4 v = av[s4];   // LDS.128 broadcast
                            acc = fmaf(v.x, wfr[s4 * 4 + 0], acc);
                            acc = fmaf(v.y, wfr[s4 * 4 + 1], acc);
                            acc = fmaf(v.z, wfr[s4 * 4 + 2], acc);
                            acc = fmaf(v.w, wfr[s4 * 4 + 3], acc);
                        }
                        orow[og * COUTV + lane] = acc;
                    }
                }
            }
        }
        g = gend;
    }
}

// ---------------------------------------------------------------------------
extern "C" void kernel_launch(void* const* d_in, const int* in_sizes, int n_in,
                              void* d_out, int out_size)
{
    const float* ang_in   = (const float*)d_in[0];
    const float* ang_out  = (const float*)d_in[1];
    const float* f_in     = (const float*)d_in[2];
    const float* W1       = (const float*)d_in[3];
    const float* b1       = (const float*)d_in[4];
    const float* W2       = (const float*)d_in[5];
    const float* b2       = (const float*)d_in[6];
    const float* W3       = (const float*)d_in[7];
    const float* b3       = (const float*)d_in[8];
    const float* Wf       = (const float*)d_in[9];
    const float* bias_out = (const float*)d_in[10];
    float* out = (float*)d_out;

    int B = in_sizes[0] / (QIN * 3);
    int N = in_sizes[2] / (B * QIN * CINV);

    cudaFuncSetAttribute(conv_kernel, cudaFuncAttributeMaxDynamicSharedMemorySize, SMEM_BYTES);

    prep_kernel<<<B * OPAD, 128>>>(ang_in, ang_out, W1, b1, W2, b2, W3, b3, B);

    int nsm = 148;
    cudaDeviceGetAttribute(&nsm, cudaDevAttrMultiProcessorCount, 0);
    int gx = nsm / 2; if (gx < 1) gx = 1;
    dim3 grid(gx, 2);
    conv_kernel<<<grid, NTH, SMEM_BYTES>>>(f_in, Wf, bias_out, out, B, N);
}

// round 6
// speedup vs baseline: 3.4294x; 1.5626x over previous
#include <cuda_runtime.h>
#include <stdint.h>

#define QIN   90
#define QOUT  60
#define OPAD  64
#define KMAX  16
#define CINV  32
#define COUTV 32
#define H1V   32
#define H2V   64
#define DMAXV 1.0f
#define MAXB  4
#define ROWF  (QIN * CINV)   // 2880 floats per (b,n) row
#define NRB   8              // rows per iteration
#define NTH   512
#define FB_FLOATS (2 * NRB * ROWF)
#define AG_FLOATS (NRB * 32 * CINV)
#define WF_FLOATS (CINV * COUTV)
#define SMEM_BYTES ((FB_FLOATS + AG_FLOATS + WF_FLOATS) * 4)

typedef unsigned long long ull;
// packed f32x2 FMA: acc = a*b + acc (elementwise on two packed floats)
#define FFMA2(acc, a, b) \
    asm("fma.rn.f32x2 %0, %1, %2, %0;" : "+l"(acc) : "l"(a), "l"(b))

// Per-(b,o) compacted tables produced by prep_kernel.
__device__ float          g_Mw[MAXB * OPAD * KMAX * CINV];  // [b][o][k][c], masked weights
__device__ unsigned short g_selo[MAXB * OPAD * KMAX];       // [b][o][k], BYTE offset i*128

// ---------------------------------------------------------------------------
// Kernel 1: distances + top-K selection + WeightNet MLP -> compact tables
// ---------------------------------------------------------------------------
__global__ void prep_kernel(const float* __restrict__ ang_in, const float* __restrict__ ang_out,
                            const float* __restrict__ W1, const float* __restrict__ b1,
                            const float* __restrict__ W2, const float* __restrict__ b2,
                            const float* __restrict__ W3, const float* __restrict__ b3,
                            int B)
{
    int bo = blockIdx.x;
    int b = bo / OPAD, o = bo % OPAD;
    int tid = threadIdx.x;

    if (o >= QOUT) {  // padded o slots: zero weights so main kernel adds nothing
        for (int i = tid; i < KMAX * CINV; i += blockDim.x)
            g_Mw[(b * OPAD + o) * KMAX * CINV + i] = 0.f;
        if (tid < KMAX) g_selo[(b * OPAD + o) * KMAX + tid] = 0;
        return;
    }

    __shared__ float sd[QIN], sbd[QIN];
    __shared__ int   ssel[KMAX];
    __shared__ float smask[KMAX], skd[KMAX], skbd[KMAX];
    __shared__ float sW2[H1V * H2V], sW3[H2V * CINV];
    __shared__ float sW1a[H1V], sW1b[H1V], sb1[H1V], sb2[H2V], sb3[CINV];
    __shared__ float sh1[KMAX][H1V], sh2[KMAX][H2V];

    for (int i = tid; i < H1V * H2V; i += 128) sW2[i] = W2[i];
    for (int i = tid; i < H2V * CINV; i += 128) sW3[i] = W3[i];
    if (tid < H2V) sb2[tid] = b2[tid];
    if (tid < CINV) sb3[tid] = b3[tid];
    if (tid < H1V) { sW1a[tid] = W1[3 * H1V + tid]; sW1b[tid] = W1[4 * H1V + tid]; sb1[tid] = b1[tid]; }

    float aox = ang_out[(b * QOUT + o) * 3 + 0];
    float aoy = ang_out[(b * QOUT + o) * 3 + 1];
    float aoz = ang_out[(b * QOUT + o) * 3 + 2];
    float nout = sqrtf(aox * aox + aoy * aoy + aoz * aoz);
    float ivo = (nout > 0.f) ? 1.f / nout : 0.f;
    float uox = aox * ivo, uoy = aoy * ivo, uoz = aoz * ivo;

    if (tid < QIN) {
        float x = ang_in[(b * QIN + tid) * 3 + 0];
        float y = ang_in[(b * QIN + tid) * 3 + 1];
        float z = ang_in[(b * QIN + tid) * 3 + 2];
        float nin = sqrtf(x * x + y * y + z * z);
        float ivi = (nin > 0.f) ? 1.f / nin : 0.f;
        float dot = (x * ivi) * uox + (y * ivi) * uoy + (z * ivi) * uoz;
        float d = acosf(fminf(fabsf(dot), 1.0f - 1e-7f));
        sd[tid] = d;
        sbd[tid] = nout - nin;
    }
    __syncthreads();

    if (tid < QIN) {
        float dt = sd[tid];
        int r = 0;
        for (int j = 0; j < QIN; j++) {
            float dj = sd[j];
            r += (dj < dt || (dj == dt && j < tid)) ? 1 : 0;
        }
        if (r < KMAX) {
            ssel[r] = tid;
            smask[r] = (dt <= DMAXV) ? 1.f : 0.f;
            skd[r] = dt;
            skbd[r] = sbd[tid];
        }
    }
    __syncthreads();

    int k = tid >> 3, ln = tid & 7;
    {
        float d = skd[k], bd = skbd[k];
        #pragma unroll
        for (int jj = 0; jj < 4; jj++) {
            int j = ln * 4 + jj;
            float h = fmaf(d, sW1a[j], fmaf(bd, sW1b[j], sb1[j]));
            sh1[k][j] = fmaxf(h, 0.f);
        }
    }
    __syncthreads();
    #pragma unroll
    for (int ll = 0; ll < 8; ll++) {
        int l = ln * 8 + ll;
        float acc = sb2[l];
        #pragma unroll 8
        for (int j = 0; j < H1V; j++) acc = fmaf(sh1[k][j], sW2[j * H2V + l], acc);
        sh2[k][l] = fmaxf(acc, 0.f);
    }
    __syncthreads();
    float m = smask[k];
    #pragma unroll
    for (int cc = 0; cc < 4; cc++) {
        int c = ln * 4 + cc;
        float acc = sb3[c];
        #pragma unroll 8
        for (int l = 0; l < H2V; l++) acc = fmaf(sh2[k][l], sW3[l * CINV + c], acc);
        g_Mw[((b * OPAD + o) * KMAX + k) * CINV + c] = m * acc;
    }
    if (ln == 0) g_selo[(b * OPAD + o) * KMAX + k] = (unsigned short)(ssel[k] * (CINV * 4));
}

// ---------------------------------------------------------------------------
// Kernel 2: persistent gather-conv + Wf epilogue, packed f32x2 datapath.
//   1 CTA/SM (512 thr, 16 warps), gridDim.y = 2 o-halves.
//   Warp covers 2 o's: half-warp = one o, lane = channel PAIR (2hl, 2hl+1).
// ---------------------------------------------------------------------------
__device__ __forceinline__ void async_rows(float* dst, const float* __restrict__ src,
                                           int nr, int tid)
{
    uint32_t s = (uint32_t)__cvta_generic_to_shared(dst);
    int total = nr * (ROWF / 4);   // float4 count, up to 5760
    #pragma unroll
    for (int i = 0; i < 12; i++) {
        int idx = tid + i * NTH;
        if (idx < total)
            asm volatile("cp.async.cg.shared.global [%0], [%1], 16;\n"
                         :: "r"(s + idx * 16), "l"(src + idx * 4) : "memory");
    }
    asm volatile("cp.async.commit_group;\n" ::: "memory");
}

// Phase 1: gather-reduce for NRB rows. Each lane accumulates a float2 channel
// pair for its half-warp's o. Reads possibly-stale smem for tail rows (results
// discarded at store time) — no tail branch needed.
__device__ __forceinline__ void phase1(const char* __restrict__ fbc, float* __restrict__ aggs,
                                       const ull (&Mp)[16], const uint32_t (&ip)[8],
                                       int ogl, int hl)
{
    ull acc[NRB];
    #pragma unroll
    for (int r = 0; r < NRB; r++) acc[r] = 0ULL;

    #pragma unroll
    for (int k = 0; k < 16; k++) {
        int off = (int)((ip[k >> 1] >> ((k & 1) * 16)) & 0xFFFFu);
        const char* p = fbc + off + hl * 8;
        ull m = Mp[k];
        #pragma unroll
        for (int r = 0; r < NRB; r++) {
            ull v = *(const ull*)(p + r * (ROWF * 4));   // LDS.64
            FFMA2(acc[r], m, v);
        }
    }
    #pragma unroll
    for (int r = 0; r < NRB; r++)
        *(ull*)(aggs + (r * 32 + ogl) * CINV + 2 * hl) = acc[r];   // STS.64
}

__global__ void __launch_bounds__(NTH, 1)
conv_kernel(const float* __restrict__ f_in, const float* __restrict__ Wf,
            const float* __restrict__ bias_out, float* __restrict__ out,
            int B, int N)
{
    extern __shared__ float smem[];
    float* fbuf = smem;                             // [2][NRB * ROWF]
    float* aggs = smem + FB_FLOATS;                 // [NRB][32][CINV]
    float* sWf  = smem + FB_FLOATS + AG_FLOATS;     // [CINV][COUTV]

    const int tid   = threadIdx.x;
    const int lane  = tid & 31;
    const int warp  = tid >> 5;          // 0..15
    const int ho    = lane >> 4;         // which o of the warp's pair
    const int hl    = lane & 15;         // channel-pair index (c = 2hl, 2hl+1)
    const int obase = blockIdx.y * 32;   // this block's o-half
    const int ogl   = warp * 2 + ho;     // local o 0..31

    for (int i = tid; i < WF_FLOATS; i += NTH) sWf[i] = Wf[i];
    const float2 bias2 = ((const float2*)bias_out)[hl];

    long long R = (long long)B * N;
    long long chunk = (R + gridDim.x - 1) / gridDim.x;
    long long r0 = (long long)blockIdx.x * chunk;
    long long r1 = r0 + chunk; if (r1 > R) r1 = R;
    if (r0 >= r1) return;

    ull      Mp[16];
    uint32_t ip[8];

    long long g = r0;
    while (g < r1) {
        int b = (int)(g / N);
        long long gend = (long long)(b + 1) * N; if (gend > r1) gend = r1;

        // Per-batch tables: weights as native float2 (per-channel pair), u16 offsets.
        {
            int og = obase + ogl;
            const ull* mp = (const ull*)(g_Mw + (size_t)(b * OPAD + og) * KMAX * CINV);
            #pragma unroll
            for (int k = 0; k < 16; k++) Mp[k] = mp[k * (CINV / 2) + hl];
            const uint32_t* q = (const uint32_t*)&g_selo[(b * OPAD + og) * KMAX];
            #pragma unroll
            for (int j = 0; j < 8; j++) ip[j] = q[j];
        }

        {
            int nfirst = (int)((gend - g) < NRB ? (gend - g) : NRB);
            async_rows(fbuf, f_in + g * ROWF, nfirst, tid);
        }

        int pb = 0;
        for (long long t = g; t < gend; t += NRB, pb ^= 1) {
            long long tn = t + NRB;
            if (tn < gend) {
                int nr = (int)((gend - tn) < NRB ? (gend - tn) : NRB);
                async_rows(fbuf + (pb ^ 1) * (NRB * ROWF), f_in + tn * ROWF, nr, tid);
                asm volatile("cp.async.wait_group 1;\n" ::: "memory");
            } else {
                asm volatile("cp.async.wait_group 0;\n" ::: "memory");
            }
            __syncthreads();   // batch ready; prev phase2 agg reads done

            const int nrows = (int)((gend - t) < NRB ? (gend - t) : NRB);

            phase1((const char*)(fbuf + pb * (NRB * ROWF)), aggs, Mp, ip, ogl, hl);

            // REQUIRED block barrier: all warps done reading fbuf[pb] before any
            // warp loops around and prefetches into it. Also publishes aggs.
            __syncthreads();

            // Phase 2: out[og, 2hl..2hl+1] = bias + sum_c' agg[og][c'] * Wf[c'][2hl..]
            // Wf hoisted per c'-quad across all rows.
            float ax[NRB], ay[NRB];
            #pragma unroll
            for (int r = 0; r < NRB; r++) { ax[r] = bias2.x; ay[r] = bias2.y; }

            const float* arow = aggs + ogl * CINV;
            #pragma unroll
            for (int cq = 0; cq < 8; cq++) {
                float2 w0 = ((const float2*)(sWf + (cq * 4 + 0) * COUTV))[hl];
                float2 w1 = ((const float2*)(sWf + (cq * 4 + 1) * COUTV))[hl];
                float2 w2 = ((const float2*)(sWf + (cq * 4 + 2) * COUTV))[hl];
                float2 w3 = ((const float2*)(sWf + (cq * 4 + 3) * COUTV))[hl];
                #pragma unroll
                for (int r = 0; r < NRB; r++) {
                    float4 a4 = *(const float4*)(arow + r * (32 * CINV) + cq * 4); // LDS.128 bcast
                    ax[r] = fmaf(a4.x, w0.x, ax[r]);  ay[r] = fmaf(a4.x, w0.y, ay[r]);
                    ax[r] = fmaf(a4.y, w1.x, ax[r]);  ay[r] = fmaf(a4.y, w1.y, ay[r]);
                    ax[r] = fmaf(a4.z, w2.x, ax[r]);  ay[r] = fmaf(a4.z, w2.y, ay[r]);
                    ax[r] = fmaf(a4.w, w3.x, ax[r]);  ay[r] = fmaf(a4.w, w3.y, ay[r]);
                }
            }

            const int og = obase + ogl;
            if (og < QOUT) {
                #pragma unroll
                for (int r = 0; r < NRB; r++) {
                    if (r < nrows) {
                        float2 v; v.x = ax[r]; v.y = ay[r];
                        *(float2*)(out + (t + r) * (QOUT * COUTV) + og * COUTV + 2 * hl) = v;
                    }
                }
            }
        }
        g = gend;
    }
}

// ---------------------------------------------------------------------------
extern "C" void kernel_launch(void* const* d_in, const int* in_sizes, int n_in,
                              void* d_out, int out_size)
{
    const float* ang_in   = (const float*)d_in[0];
    const float* ang_out  = (const float*)d_in[1];
    const float* f_in     = (const float*)d_in[2];
    const float* W1       = (const float*)d_in[3];
    const float* b1       = (const float*)d_in[4];
    const float* W2       = (const float*)d_in[5];
    const float* b2       = (const float*)d_in[6];
    const float* W3       = (const float*)d_in[7];
    const float* b3       = (const float*)d_in[8];
    const float* Wf       = (const float*)d_in[9];
    const float* bias_out = (const float*)d_in[10];
    float* out = (float*)d_out;

    int B = in_sizes[0] / (QIN * 3);
    int N = in_sizes[2] / (B * QIN * CINV);

    cudaFuncSetAttribute(conv_kernel, cudaFuncAttributeMaxDynamicSharedMemorySize, SMEM_BYTES);

    prep_kernel<<<B * OPAD, 128>>>(ang_in, ang_out, W1, b1, W2, b2, W3, b3, B);

    int nsm = 148;
    cudaDeviceGetAttribute(&nsm, cudaDevAttrMultiProcessorCount, 0);
    int gx = nsm / 2; if (gx < 1) gx = 1;
    dim3 grid(gx, 2);
    conv_kernel<<<grid, NTH, SMEM_BYTES>>>(f_in, Wf, bias_out, out, B, N);
}